// round 1
// baseline (speedup 1.0000x reference)
#include <cuda_runtime.h>

// Problem constants
#define BB 4
#define HH 16
#define NSEQ 8192
#define DD 64
#define EE 64
#define BH (BB*HH)                       // 64
#define OUTG_ELEMS (BH*NSEQ*EE)          // 33554432
#define KV_ELEMS (BH*DD*EE)              // 262144
#define NORM_ELEMS (BH*DD)               // 4096

#define TILE 64
#define CHUNKS 32
#define ROWS_PER_BLOCK (NSEQ/CHUNKS)     // 256
#define TILES_PER_BLOCK (ROWS_PER_BLOCK/TILE) // 4
#define THREADS 128

// Shared layout (float2 units):
//   sdup[64][65]  : elu(x)+1, transposed [d][row], value duplicated in .x/.y
//   skv [64][33]  : past_kv [d][epair]
//   sv  [64][33]  : v' rows [row][epair]
// then floats: snorm[64], srcp[64]
#define SDUP_STRIDE 65
#define SKV_STRIDE 33
#define SV_STRIDE 33
#define SMEM_F2 (64*SDUP_STRIDE + 64*SKV_STRIDE + 64*SV_STRIDE)
#define SMEM_BYTES (SMEM_F2*8 + 128*4)

// Packed f32x2 FMA: d = a*b + d (2 scalar FMAs per instruction)
__device__ __forceinline__ void fma2(float2 &d, const float2 &a, const float2 &b) {
    asm("fma.rn.f32x2 %0, %1, %2, %0;"
        : "+l"(*reinterpret_cast<unsigned long long *>(&d))
        : "l"(*reinterpret_cast<const unsigned long long *>(&a)),
          "l"(*reinterpret_cast<const unsigned long long *>(&b)));
}

__global__ void __launch_bounds__(THREADS)
fw_kernel(const float* __restrict__ keys,
          const float* __restrict__ values,
          const float* __restrict__ queries,
          const float* __restrict__ outp,
          const float* __restrict__ past_kv,
          const float* __restrict__ past_norm,
          const float* __restrict__ head_gates,
          float* __restrict__ dout)
{
    extern __shared__ float2 smemf2[];
    float2* sdup  = smemf2;
    float2* skv   = sdup + 64*SDUP_STRIDE;
    float2* sv    = skv + 64*SKV_STRIDE;
    float*  snorm = reinterpret_cast<float*>(sv + 64*SV_STRIDE);
    float*  srcp  = snorm + 64;

    const int bh  = blockIdx.y;
    const int tid = threadIdx.x;
    const int rg  = tid >> 3;   // 0..15  (rows group in GEMM phase, d group in outer phase)
    const int eg  = tid & 7;    // 0..7   (e-pair set: {eg, eg+8, eg+16, eg+24})

    // past_kv -> shared (packed e pairs)
    const float* pkv = past_kv + bh * (DD*EE);
    for (int i = tid; i < DD*EE/2; i += THREADS) {
        int d = i >> 5, ep = i & 31;
        skv[d*SKV_STRIDE + ep] = *reinterpret_cast<const float2*>(pkv + d*EE + ep*2);
    }
    if (tid < 64) snorm[tid] = past_norm[bh*DD + tid];

    float gate;
    {
        float hg = head_gates[bh % HH];
        gate = 1.0f / (1.0f + __expf(-hg));
    }
    const float one_minus_gate = 1.0f - gate;

    float2 acc[4][4];
    #pragma unroll
    for (int i = 0; i < 4; i++)
        #pragma unroll
        for (int j = 0; j < 4; j++) acc[i][j] = make_float2(0.f, 0.f);
    float normAcc = 0.f;

    __syncthreads();

    const long rowbase0 = (long)bh * NSEQ + (long)blockIdx.x * ROWS_PER_BLOCK;

    for (int t = 0; t < TILES_PER_BLOCK; ++t) {
        const long rowb = rowbase0 + t * TILE;
        const float* qptr = queries + rowb * DD;
        const float* kptr = keys    + rowb * DD;

        // ================= Q path =================
        // load + elu + transpose + duplicate
        #pragma unroll 8
        for (int i = tid; i < TILE*DD; i += THREADS) {
            int row = i >> 6, d = i & 63;
            float x = qptr[i];
            float ex = (x > 0.f) ? (x + 1.f) : __expf(x);
            sdup[d*SDUP_STRIDE + row] = make_float2(ex, ex);
        }
        __syncthreads();

        if (tid < 64) {
            float s = 0.f;
            #pragma unroll 8
            for (int d = 0; d < DD; ++d) s += sdup[d*SDUP_STRIDE + tid].x * snorm[d];
            srcp[tid] = 1.0f / fmaxf(s, 1e-10f);
        }
        __syncthreads();

        // numerQ GEMM: thread = rows rg*4..+3  x  epairs {eg+8j}
        {
            float2 num[4][4];
            #pragma unroll
            for (int i = 0; i < 4; i++)
                #pragma unroll
                for (int j = 0; j < 4; j++) num[i][j] = make_float2(0.f, 0.f);

            const float2* ap = sdup + rg*4;
            const float2* bp = skv + eg;
            #pragma unroll 8
            for (int d = 0; d < DD; ++d) {
                float2 a0 = ap[d*SDUP_STRIDE + 0];
                float2 a1 = ap[d*SDUP_STRIDE + 1];
                float2 a2 = ap[d*SDUP_STRIDE + 2];
                float2 a3 = ap[d*SDUP_STRIDE + 3];
                float2 b0 = bp[d*SKV_STRIDE + 0];
                float2 b1 = bp[d*SKV_STRIDE + 8];
                float2 b2 = bp[d*SKV_STRIDE + 16];
                float2 b3 = bp[d*SKV_STRIDE + 24];
                fma2(num[0][0], a0, b0); fma2(num[0][1], a0, b1); fma2(num[0][2], a0, b2); fma2(num[0][3], a0, b3);
                fma2(num[1][0], a1, b0); fma2(num[1][1], a1, b1); fma2(num[1][2], a1, b2); fma2(num[1][3], a1, b3);
                fma2(num[2][0], a2, b0); fma2(num[2][1], a2, b1); fma2(num[2][2], a2, b2); fma2(num[2][3], a2, b3);
                fma2(num[3][0], a3, b0); fma2(num[3][1], a3, b1); fma2(num[3][2], a3, b2); fma2(num[3][3], a3, b3);
            }
            // epilogue: out_g = out*g + numQ * (rcp*(1-g))
            #pragma unroll
            for (int i = 0; i < 4; i++) {
                int row = rg*4 + i;
                float c1 = srcp[row] * one_minus_gate;
                float2 cc = make_float2(c1, c1);
                const float* orow = outp + (rowb + row) * EE;
                float*       grow = dout + (rowb + row) * EE;
                #pragma unroll
                for (int j = 0; j < 4; j++) {
                    int e = 2*(eg + 8*j);
                    float2 o = *reinterpret_cast<const float2*>(orow + e);
                    float2 r = make_float2(o.x * gate, o.y * gate);
                    fma2(r, num[i][j], cc);
                    *reinterpret_cast<float2*>(grow + e) = r;
                }
            }
        }
        __syncthreads();   // before overwriting sdup

        // ================= K path =================
        #pragma unroll 8
        for (int i = tid; i < TILE*DD; i += THREADS) {
            int row = i >> 6, d = i & 63;
            float x = kptr[i];
            float ex = (x > 0.f) ? (x + 1.f) : __expf(x);
            sdup[d*SDUP_STRIDE + row] = make_float2(ex, ex);
        }
        __syncthreads();

        if (tid < 64) {
            float s = 0.f;
            #pragma unroll 8
            for (int d = 0; d < DD; ++d) s += sdup[d*SDUP_STRIDE + tid].x * snorm[d];
            srcp[tid] = 1.0f / fmaxf(s, 1e-10f);
        } else {
            int d = tid - 64;
            float s = 0.f;
            #pragma unroll 8
            for (int row = 0; row < TILE; ++row) s += sdup[d*SDUP_STRIDE + row].x;
            normAcc += s;
        }
        __syncthreads();

        // numerK GEMM + v' = values - numerK * rcp(denomK)
        {
            float2 num[4][4];
            #pragma unroll
            for (int i = 0; i < 4; i++)
                #pragma unroll
                for (int j = 0; j < 4; j++) num[i][j] = make_float2(0.f, 0.f);

            const float2* ap = sdup + rg*4;
            const float2* bp = skv + eg;
            #pragma unroll 8
            for (int d = 0; d < DD; ++d) {
                float2 a0 = ap[d*SDUP_STRIDE + 0];
                float2 a1 = ap[d*SDUP_STRIDE + 1];
                float2 a2 = ap[d*SDUP_STRIDE + 2];
                float2 a3 = ap[d*SDUP_STRIDE + 3];
                float2 b0 = bp[d*SKV_STRIDE + 0];
                float2 b1 = bp[d*SKV_STRIDE + 8];
                float2 b2 = bp[d*SKV_STRIDE + 16];
                float2 b3 = bp[d*SKV_STRIDE + 24];
                fma2(num[0][0], a0, b0); fma2(num[0][1], a0, b1); fma2(num[0][2], a0, b2); fma2(num[0][3], a0, b3);
                fma2(num[1][0], a1, b0); fma2(num[1][1], a1, b1); fma2(num[1][2], a1, b2); fma2(num[1][3], a1, b3);
                fma2(num[2][0], a2, b0); fma2(num[2][1], a2, b1); fma2(num[2][2], a2, b2); fma2(num[2][3], a2, b3);
                fma2(num[3][0], a3, b0); fma2(num[3][1], a3, b1); fma2(num[3][2], a3, b2); fma2(num[3][3], a3, b3);
            }
            #pragma unroll
            for (int i = 0; i < 4; i++) {
                int row = rg*4 + i;
                float nr = -srcp[row];
                float2 nn = make_float2(nr, nr);
                const float* vrow = values + (rowb + row) * EE;
                #pragma unroll
                for (int j = 0; j < 4; j++) {
                    int ep = eg + 8*j;
                    float2 val = *reinterpret_cast<const float2*>(vrow + 2*ep);
                    fma2(val, num[i][j], nn);  // val = values - num*rcp
                    sv[row*SV_STRIDE + ep] = val;
                }
            }
        }
        __syncthreads();

        // outer product accumulate: thread = d in {rg*4..+3} x epairs {eg+8j}
        {
            const float2* kp = sdup + rg*4*SDUP_STRIDE;
            const float2* vp = sv + eg;
            #pragma unroll 8
            for (int row = 0; row < TILE; ++row) {
                float2 k0 = kp[0*SDUP_STRIDE + row];
                float2 k1 = kp[1*SDUP_STRIDE + row];
                float2 k2 = kp[2*SDUP_STRIDE + row];
                float2 k3 = kp[3*SDUP_STRIDE + row];
                float2 v0 = vp[row*SV_STRIDE + 0];
                float2 v1 = vp[row*SV_STRIDE + 8];
                float2 v2 = vp[row*SV_STRIDE + 16];
                float2 v3 = vp[row*SV_STRIDE + 24];
                fma2(acc[0][0], k0, v0); fma2(acc[0][1], k0, v1); fma2(acc[0][2], k0, v2); fma2(acc[0][3], k0, v3);
                fma2(acc[1][0], k1, v0); fma2(acc[1][1], k1, v1); fma2(acc[1][2], k1, v2); fma2(acc[1][3], k1, v3);
                fma2(acc[2][0], k2, v0); fma2(acc[2][1], k2, v1); fma2(acc[2][2], k2, v2); fma2(acc[2][3], k2, v3);
                fma2(acc[3][0], k3, v0); fma2(acc[3][1], k3, v1); fma2(acc[3][2], k3, v2); fma2(acc[3][3], k3, v3);
            }
        }
        __syncthreads();   // before next tile overwrites sdup/sv
    }

    // Flush accumulators: new_kv partials (base = past_kv copied by memcpy)
    float* okv = dout + OUTG_ELEMS + bh * (DD*EE);
    #pragma unroll
    for (int i = 0; i < 4; i++) {
        int d = rg*4 + i;
        #pragma unroll
        for (int j = 0; j < 4; j++) {
            int e = 2*(eg + 8*j);
            atomicAdd(&okv[d*EE + e],     acc[i][j].x);
            atomicAdd(&okv[d*EE + e + 1], acc[i][j].y);
        }
    }
    if (tid >= 64) {
        atomicAdd(dout + OUTG_ELEMS + KV_ELEMS + bh*DD + (tid - 64), normAcc);
    }
}

extern "C" void kernel_launch(void* const* d_in, const int* in_sizes, int n_in,
                              void* d_out, int out_size)
{
    const float* keys      = (const float*)d_in[0];
    const float* values    = (const float*)d_in[1];
    const float* queries   = (const float*)d_in[2];
    const float* outp      = (const float*)d_in[3];
    const float* past_kv   = (const float*)d_in[4];
    const float* past_norm = (const float*)d_in[5];
    const float* gates     = (const float*)d_in[6];
    float* dout = (float*)d_out;

    // Seed new_kv / new_norm output regions with past values (atomics add partials on top)
    cudaMemcpyAsync(dout + OUTG_ELEMS, past_kv, KV_ELEMS * sizeof(float),
                    cudaMemcpyDeviceToDevice);
    cudaMemcpyAsync(dout + OUTG_ELEMS + KV_ELEMS, past_norm, NORM_ELEMS * sizeof(float),
                    cudaMemcpyDeviceToDevice);

    cudaFuncSetAttribute(fw_kernel, cudaFuncAttributeMaxDynamicSharedMemorySize, SMEM_BYTES);

    dim3 grid(CHUNKS, BH);
    fw_kernel<<<grid, THREADS, SMEM_BYTES>>>(keys, values, queries, outp,
                                             past_kv, past_norm, gates, dout);
}

// round 2
// speedup vs baseline: 1.2661x; 1.2661x over previous
#include <cuda_runtime.h>

// Problem constants
#define BB 4
#define HH 16
#define NSEQ 8192
#define DD 64
#define EE 64
#define BH (BB*HH)                       // 64
#define OUTG_ELEMS (BH*NSEQ*EE)          // 33554432
#define KV_ELEMS (BH*DD*EE)              // 262144
#define NORM_ELEMS (BH*DD)               // 4096

#define TILE 64
#define CHUNKS 32
#define ROWS_PER_BLOCK (NSEQ/CHUNKS)     // 256
#define TILES_PER_BLOCK (ROWS_PER_BLOCK/TILE) // 4
#define THREADS 128

// Shared layout:
//   sAq[64][65] float : elu(q)+1, row-major [row][d]
//   sAk[64][65] float : elu(k)+1, row-major [row][d]
//   skv [64][33] float2 : past_kv [d][epair]
//   sv  [64][33] float2 : v' rows [row][epair]
//   snorm[64], srcpq[64], srcpk[64] float
#define SA_STRIDE 65
#define SKV_STRIDE 33
#define SV_STRIDE 33
#define SMEM_BYTES (2*64*SA_STRIDE*4 + 2*64*SKV_STRIDE*8 + 3*64*4 + 64)

// Packed f32x2 FMA: d = a*b + d (2 scalar FMAs per instruction)
__device__ __forceinline__ void fma2(float2 &d, const float2 &a, const float2 &b) {
    asm("fma.rn.f32x2 %0, %1, %2, %0;"
        : "+l"(*reinterpret_cast<unsigned long long *>(&d))
        : "l"(*reinterpret_cast<const unsigned long long *>(&a)),
          "l"(*reinterpret_cast<const unsigned long long *>(&b)));
}

__device__ __forceinline__ float elu1(float x) {
    return (x > 0.f) ? (x + 1.f) : __expf(x);
}

__global__ void __launch_bounds__(THREADS, 3)
fw_kernel(const float* __restrict__ keys,
          const float* __restrict__ values,
          const float* __restrict__ queries,
          const float* __restrict__ outp,
          const float* __restrict__ past_kv,
          const float* __restrict__ past_norm,
          const float* __restrict__ head_gates,
          float* __restrict__ dout)
{
    extern __shared__ float smem[];
    float*  sAq  = smem;                                   // 64*65 floats
    float*  sAk  = sAq + 64*SA_STRIDE;                     // 64*65 floats
    float2* skv  = reinterpret_cast<float2*>(sAk + 64*SA_STRIDE);
    float2* sv   = skv + 64*SKV_STRIDE;
    float*  snorm = reinterpret_cast<float*>(sv + 64*SV_STRIDE);
    float*  srcpq = snorm + 64;
    float*  srcpk = srcpq + 64;

    const int bh  = blockIdx.y;
    const int tid = threadIdx.x;
    const int rg  = tid >> 3;   // 0..15 : row group (GEMM) / d group (outer)
    const int eg  = tid & 7;    // 0..7  : e-pair set {eg, eg+8, eg+16, eg+24}

    // past_kv -> shared
    const float* pkv = past_kv + bh * (DD*EE);
    for (int i = tid; i < DD*EE/2; i += THREADS) {
        int d = i >> 5, ep = i & 31;
        skv[d*SKV_STRIDE + ep] = *reinterpret_cast<const float2*>(pkv + d*EE + ep*2);
    }
    if (tid < 64) snorm[tid] = past_norm[bh*DD + tid];

    float gate;
    {
        float hg = head_gates[bh % HH];
        gate = 1.0f / (1.0f + __expf(-hg));
    }
    const float one_minus_gate = 1.0f - gate;

    float2 acc[4][4];
    #pragma unroll
    for (int i = 0; i < 4; i++)
        #pragma unroll
        for (int j = 0; j < 4; j++) acc[i][j] = make_float2(0.f, 0.f);
    float normAcc = 0.f;   // partial norm sum for d = tid & 63

    __syncthreads();

    const long rowbase0 = (long)bh * NSEQ + (long)blockIdx.x * ROWS_PER_BLOCK;

    for (int t = 0; t < TILES_PER_BLOCK; ++t) {
        const long rowb = rowbase0 + t * TILE;
        const float* qptr = queries + rowb * DD;
        const float* kptr = keys    + rowb * DD;

        // ---- load Q and K tiles (elu), fold K per-d norm partials ----
        #pragma unroll 8
        for (int i = tid; i < TILE*DD; i += THREADS) {
            int row = i >> 6, d = i & 63;
            sAq[row*SA_STRIDE + d] = elu1(qptr[i]);
            float ek = elu1(kptr[i]);
            sAk[row*SA_STRIDE + d] = ek;
            normAcc += ek;                 // thread's d = tid&63 is constant
        }
        __syncthreads();

        // ---- denominators ----
        if (tid < 64) {
            const float* ar = sAq + tid*SA_STRIDE;
            float s = 0.f;
            #pragma unroll 16
            for (int d = 0; d < DD; ++d) s += ar[d] * snorm[d];
            srcpq[tid] = 1.0f / fmaxf(s, 1e-10f);
        } else {
            int row = tid - 64;
            const float* ar = sAk + row*SA_STRIDE;
            float s = 0.f;
            #pragma unroll 16
            for (int d = 0; d < DD; ++d) s += ar[d] * snorm[d];
            srcpk[row] = 1.0f / fmaxf(s, 1e-10f);
        }
        __syncthreads();

        // ---- fused Q+K numerator GEMMs (share B loads) ----
        {
            float2 nq[4][4], nk[4][4];
            #pragma unroll
            for (int i = 0; i < 4; i++)
                #pragma unroll
                for (int j = 0; j < 4; j++) {
                    nq[i][j] = make_float2(0.f, 0.f);
                    nk[i][j] = make_float2(0.f, 0.f);
                }

            const float*  aq = sAq + (rg*4)*SA_STRIDE;
            const float*  ak = sAk + (rg*4)*SA_STRIDE;
            const float2* bp = skv + eg;
            #pragma unroll 8
            for (int d = 0; d < DD; ++d) {
                float2 b0 = bp[d*SKV_STRIDE + 0];
                float2 b1 = bp[d*SKV_STRIDE + 8];
                float2 b2 = bp[d*SKV_STRIDE + 16];
                float2 b3 = bp[d*SKV_STRIDE + 24];
                #pragma unroll
                for (int i = 0; i < 4; ++i) {
                    float a = aq[i*SA_STRIDE + d];
                    float2 av = make_float2(a, a);
                    fma2(nq[i][0], av, b0); fma2(nq[i][1], av, b1);
                    fma2(nq[i][2], av, b2); fma2(nq[i][3], av, b3);
                    float c = ak[i*SA_STRIDE + d];
                    float2 cv = make_float2(c, c);
                    fma2(nk[i][0], cv, b0); fma2(nk[i][1], cv, b1);
                    fma2(nk[i][2], cv, b2); fma2(nk[i][3], cv, b3);
                }
            }

            // ---- Q epilogue: out_g = out*g + numQ * (rcpQ*(1-g)) ----
            #pragma unroll
            for (int i = 0; i < 4; i++) {
                int row = rg*4 + i;
                float c1 = srcpq[row] * one_minus_gate;
                float2 cc = make_float2(c1, c1);
                const float* orow = outp + (rowb + row) * EE;
                float*       grow = dout + (rowb + row) * EE;
                #pragma unroll
                for (int j = 0; j < 4; j++) {
                    int e = 2*(eg + 8*j);
                    float2 o = *reinterpret_cast<const float2*>(orow + e);
                    float2 r = make_float2(o.x * gate, o.y * gate);
                    fma2(r, nq[i][j], cc);
                    *reinterpret_cast<float2*>(grow + e) = r;
                }
            }

            // ---- K epilogue: v' = values - numK * rcpK -> sv ----
            #pragma unroll
            for (int i = 0; i < 4; i++) {
                int row = rg*4 + i;
                float nr = -srcpk[row];
                float2 nn = make_float2(nr, nr);
                const float* vrow = values + (rowb + row) * EE;
                #pragma unroll
                for (int j = 0; j < 4; j++) {
                    int ep = eg + 8*j;
                    float2 val = *reinterpret_cast<const float2*>(vrow + 2*ep);
                    fma2(val, nk[i][j], nn);
                    sv[row*SV_STRIDE + ep] = val;
                }
            }
        }
        __syncthreads();

        // ---- outer product: acc[d][e] += elu(k)[row][d] * v'[row][e] ----
        {
            const float*  kp = sAk + rg*4;   // [row][d], d = rg*4 + i
            const float2* vp = sv + eg;
            #pragma unroll 8
            for (int row = 0; row < TILE; ++row) {
                float2 v0 = vp[row*SV_STRIDE + 0];
                float2 v1 = vp[row*SV_STRIDE + 8];
                float2 v2 = vp[row*SV_STRIDE + 16];
                float2 v3 = vp[row*SV_STRIDE + 24];
                #pragma unroll
                for (int i = 0; i < 4; ++i) {
                    float k = kp[row*SA_STRIDE + i];
                    float2 kv2 = make_float2(k, k);
                    fma2(acc[i][0], kv2, v0); fma2(acc[i][1], kv2, v1);
                    fma2(acc[i][2], kv2, v2); fma2(acc[i][3], kv2, v3);
                }
            }
        }
        __syncthreads();   // before next tile overwrites sAq/sAk/sv
    }

    // ---- flush: new_kv partials (base = past_kv copied by memcpy) ----
    float* okv = dout + OUTG_ELEMS + bh * (DD*EE);
    #pragma unroll
    for (int i = 0; i < 4; i++) {
        int d = rg*4 + i;
        #pragma unroll
        for (int j = 0; j < 4; j++) {
            int e = 2*(eg + 8*j);
            atomicAdd(&okv[d*EE + e],     acc[i][j].x);
            atomicAdd(&okv[d*EE + e + 1], acc[i][j].y);
        }
    }
    // norm partials: thread covers d = tid&63 (two threads per d)
    atomicAdd(dout + OUTG_ELEMS + KV_ELEMS + bh*DD + (tid & 63), normAcc);
}

extern "C" void kernel_launch(void* const* d_in, const int* in_sizes, int n_in,
                              void* d_out, int out_size)
{
    const float* keys      = (const float*)d_in[0];
    const float* values    = (const float*)d_in[1];
    const float* queries   = (const float*)d_in[2];
    const float* outp      = (const float*)d_in[3];
    const float* past_kv   = (const float*)d_in[4];
    const float* past_norm = (const float*)d_in[5];
    const float* gates     = (const float*)d_in[6];
    float* dout = (float*)d_out;

    // Seed new_kv / new_norm output regions with past values (atomics add partials on top)
    cudaMemcpyAsync(dout + OUTG_ELEMS, past_kv, KV_ELEMS * sizeof(float),
                    cudaMemcpyDeviceToDevice);
    cudaMemcpyAsync(dout + OUTG_ELEMS + KV_ELEMS, past_norm, NORM_ELEMS * sizeof(float),
                    cudaMemcpyDeviceToDevice);

    cudaFuncSetAttribute(fw_kernel, cudaFuncAttributeMaxDynamicSharedMemorySize, SMEM_BYTES);

    dim3 grid(CHUNKS, BH);
    fw_kernel<<<grid, THREADS, SMEM_BYTES>>>(keys, values, queries, outp,
                                             past_kv, past_norm, gates, dout);
}

// round 4
// speedup vs baseline: 1.9782x; 1.5624x over previous
#include <cuda_runtime.h>
#include <cstdint>

// ---------------- problem constants ----------------
#define BB 4
#define HH 16
#define NSEQ 8192
#define DD 64
#define EE 64
#define BH (BB*HH)                       // 64
#define OUTG_ELEMS (BH*NSEQ*EE)          // 33554432
#define KV_ELEMS (BH*DD*EE)              // 262144
#define NORM_ELEMS (BH*DD)               // 4096

#define CHUNKS 32
#define ROWS_PER_BLOCK 256
#define TILE 64
#define NTILES 4
#define THREADS 128

#define STRIDE 68                        // floats per smem row (pad 4)
// float offsets inside dynamic smem
#define F_SQ0 0                          // Q raw->tf32, double buffered
#define F_SK0 (2*64*STRIDE)              // K, double buffered
#define F_B1  (4*64*STRIDE)              // past_kv^T (tf32) + norm row 64 : 72 rows
#define F_VT  (F_B1 + 72*STRIDE)         // v'^T (tf32) + ones row 64     : 72 rows
#define SMEM_FLOATS (F_VT + 72*STRIDE)   // 27200
#define SMEM_BYTES (SMEM_FLOATS*4)       // 108800

// ---------------- helpers ----------------
__device__ __forceinline__ uint32_t smem_u32(const void* p) {
    uint32_t a;
    asm("{ .reg .u64 t; cvta.to.shared.u64 t, %1; cvt.u32.u64 %0, t; }" : "=r"(a) : "l"(p));
    return a;
}
__device__ __forceinline__ uint32_t cvt_tf32(float x) {
    uint32_t u;
    asm("cvt.rna.tf32.f32 %0, %1;" : "=r"(u) : "f"(x));
    return u;
}
__device__ __forceinline__ float elu1(float x) { return (x > 0.f) ? (x + 1.f) : __expf(x); }
__device__ __forceinline__ void cp16(uint32_t dst, const void* src) {
    asm volatile("cp.async.cg.shared.global [%0], [%1], 16;" :: "r"(dst), "l"(src));
}
__device__ __forceinline__ void mma8(float* d, uint32_t a0, uint32_t a1, uint32_t a2, uint32_t a3,
                                     uint32_t b0, uint32_t b1) {
    asm volatile("mma.sync.aligned.m16n8k8.row.col.f32.tf32.tf32.f32 "
                 "{%0,%1,%2,%3}, {%4,%5,%6,%7}, {%8,%9}, {%0,%1,%2,%3};"
                 : "+f"(d[0]), "+f"(d[1]), "+f"(d[2]), "+f"(d[3])
                 : "r"(a0), "r"(a1), "r"(a2), "r"(a3), "r"(b0), "r"(b1));
}

__global__ void __launch_bounds__(THREADS)
fw_kernel(const float* __restrict__ keys,
          const float* __restrict__ values,
          const float* __restrict__ queries,
          const float* __restrict__ outp,
          const float* __restrict__ past_kv,
          const float* __restrict__ past_norm,
          const float* __restrict__ head_gates,
          float* __restrict__ dout)
{
    extern __shared__ float smem[];
    const uint32_t sbase = smem_u32(smem);
    const int tid  = threadIdx.x;
    const int lane = tid & 31;
    const int w    = tid >> 5;           // warp 0..3
    const int bh   = blockIdx.y;

    // ---- stage B1 = past_kv^T (tf32) + norm row; sVT constant rows ----
    {
        const float* pkv = past_kv + (size_t)bh * (DD*EE);
        for (int i = tid; i < DD*EE; i += THREADS) {
            int d = i >> 6, e = i & 63;
            smem[F_B1 + e*STRIDE + d] = __uint_as_float(cvt_tf32(pkv[i]));
        }
        if (tid < 64)
            smem[F_B1 + 64*STRIDE + tid] = __uint_as_float(cvt_tf32(past_norm[bh*DD + tid]));
        for (int i = tid; i < 7*STRIDE; i += THREADS) {
            smem[F_B1 + 65*STRIDE + i] = 0.0f;
            smem[F_VT + 65*STRIDE + i] = 0.0f;
        }
        for (int i = tid; i < 64; i += THREADS)
            smem[F_VT + 64*STRIDE + i] = 1.0f;   // ones row -> new_norm column
    }

    float gate;
    {
        float hg = head_gates[bh & (HH-1)];
        gate = 1.0f / (1.0f + __expf(-hg));
    }
    const float omg = 1.0f - gate;

    const long rowbase = (long)bh * NSEQ + (long)blockIdx.x * ROWS_PER_BLOCK;

    auto stage = [&](int buf, long rowb) {
        const float* qs = queries + rowb * DD;
        const float* ks = keys    + rowb * DD;
        uint32_t qd = sbase + (uint32_t)(F_SQ0 + buf*(64*STRIDE)) * 4u;
        uint32_t kd = sbase + (uint32_t)(F_SK0 + buf*(64*STRIDE)) * 4u;
        #pragma unroll
        for (int j = 0; j < 8; ++j) {
            int idx = j*THREADS + tid;
            int row = idx >> 4, seg = idx & 15;
            cp16(qd + (uint32_t)row*(STRIDE*4) + seg*16, qs + row*DD + seg*4);
            cp16(kd + (uint32_t)row*(STRIDE*4) + seg*16, ks + row*DD + seg*4);
        }
        asm volatile("cp.async.commit_group;" ::: "memory");
    };

    stage(0, rowbase);

    float d2[9][4];
    #pragma unroll
    for (int n = 0; n < 9; ++n)
        #pragma unroll
        for (int c = 0; c < 4; ++c) d2[n][c] = 0.f;

    const bool isQ = (w < 2);
    const int rloc = 32 * (w & 1);       // local base row within Q-half or K-half

    for (int t = 0; t < NTILES; ++t) {
        const long rowb = rowbase + (long)t * TILE;
        if (t + 1 < NTILES) {
            stage((t+1) & 1, rowb + TILE);
            asm volatile("cp.async.wait_group 1;" ::: "memory");
        } else {
            asm volatile("cp.async.wait_group 0;" ::: "memory");
        }
        __syncthreads();

        float* q_ = smem + F_SQ0 + (t & 1)*(64*STRIDE);
        float* k_ = smem + F_SK0 + (t & 1)*(64*STRIDE);

        // ---- in-place convert: elu + tf32 (once per element) ----
        #pragma unroll
        for (int j0 = 0; j0 < 8; ++j0) {
            int j = j0*THREADS + tid;
            int row = j >> 4, c4 = j & 15;
            float4* pq = reinterpret_cast<float4*>(q_ + row*STRIDE + c4*4);
            float4 v = *pq;
            v.x = __uint_as_float(cvt_tf32(elu1(v.x)));
            v.y = __uint_as_float(cvt_tf32(elu1(v.y)));
            v.z = __uint_as_float(cvt_tf32(elu1(v.z)));
            v.w = __uint_as_float(cvt_tf32(elu1(v.w)));
            *pq = v;
            float4* pk = reinterpret_cast<float4*>(k_ + row*STRIDE + c4*4);
            float4 u = *pk;
            u.x = __uint_as_float(cvt_tf32(elu1(u.x)));
            u.y = __uint_as_float(cvt_tf32(elu1(u.y)));
            u.z = __uint_as_float(cvt_tf32(elu1(u.z)));
            u.w = __uint_as_float(cvt_tf32(elu1(u.w)));
            *pk = u;
        }
        __syncthreads();

        // ---- GEMM1: D1 = [Q;K] x B1  (N=72, col 64 = denominator) ----
        const float* A = isQ ? q_ : k_;
        float d1[2][9][4];
        #pragma unroll
        for (int mt = 0; mt < 2; ++mt)
            #pragma unroll
            for (int n = 0; n < 9; ++n)
                #pragma unroll
                for (int c = 0; c < 4; ++c) d1[mt][n][c] = 0.f;

        #pragma unroll
        for (int ks8 = 0; ks8 < 8; ++ks8) {
            uint32_t bf[9][2];
            #pragma unroll
            for (int nt = 0; nt < 9; ++nt) {
                const float* bp = smem + F_B1 + (8*nt + (lane>>2))*STRIDE + 8*ks8 + (lane&3);
                bf[nt][0] = __float_as_uint(bp[0]);
                bf[nt][1] = __float_as_uint(bp[4]);
            }
            #pragma unroll
            for (int mt = 0; mt < 2; ++mt) {
                const float* ap = A + (rloc + 16*mt + (lane>>2))*STRIDE + 8*ks8 + (lane&3);
                uint32_t a0 = __float_as_uint(ap[0]);
                uint32_t a1 = __float_as_uint(ap[8*STRIDE]);
                uint32_t a2 = __float_as_uint(ap[4]);
                uint32_t a3 = __float_as_uint(ap[8*STRIDE + 4]);
                #pragma unroll
                for (int nt = 0; nt < 9; ++nt)
                    mma8(d1[mt][nt], a0, a1, a2, a3, bf[nt][0], bf[nt][1]);
            }
        }

        // ---- epilogue ----
        #pragma unroll
        for (int mt = 0; mt < 2; ++mt) {
            float den0 = __shfl_sync(0xffffffffu, d1[mt][8][0], lane & 28);
            float den1 = __shfl_sync(0xffffffffu, d1[mt][8][2], lane & 28);
            float r0 = 1.0f / fmaxf(den0, 1e-10f);
            float r1 = 1.0f / fmaxf(den1, 1e-10f);
            int lrow = rloc + 16*mt + (lane >> 2);   // local row in tile
            int ec = lane & 3;
            if (isQ) {
                float c0 = r0 * omg, c1 = r1 * omg;
                const float2* o0 = (const float2*)(outp + (size_t)(rowb + lrow) * EE);
                const float2* o1 = (const float2*)(outp + (size_t)(rowb + lrow + 8) * EE);
                float2* g0 = (float2*)(dout + (size_t)(rowb + lrow) * EE);
                float2* g1 = (float2*)(dout + (size_t)(rowb + lrow + 8) * EE);
                #pragma unroll
                for (int nt = 0; nt < 8; ++nt) {
                    float2 a = o0[4*nt + ec];
                    float2 b = o1[4*nt + ec];
                    float2 ra, rb;
                    ra.x = a.x * gate + d1[mt][nt][0] * c0;
                    ra.y = a.y * gate + d1[mt][nt][1] * c0;
                    rb.x = b.x * gate + d1[mt][nt][2] * c1;
                    rb.y = b.y * gate + d1[mt][nt][3] * c1;
                    g0[4*nt + ec] = ra;
                    g1[4*nt + ec] = rb;
                }
            } else {
                const float2* v0 = (const float2*)(values + (size_t)(rowb + lrow) * EE);
                const float2* v1 = (const float2*)(values + (size_t)(rowb + lrow + 8) * EE);
                #pragma unroll
                for (int nt = 0; nt < 8; ++nt) {
                    float2 a = v0[4*nt + ec];
                    float2 b = v1[4*nt + ec];
                    int e = 8*nt + 2*ec;
                    float p00 = a.x - d1[mt][nt][0] * r0;
                    float p01 = a.y - d1[mt][nt][1] * r0;
                    float p10 = b.x - d1[mt][nt][2] * r1;
                    float p11 = b.y - d1[mt][nt][3] * r1;
                    smem[F_VT + e*STRIDE + lrow]         = __uint_as_float(cvt_tf32(p00));
                    smem[F_VT + (e+1)*STRIDE + lrow]     = __uint_as_float(cvt_tf32(p01));
                    smem[F_VT + e*STRIDE + lrow + 8]     = __uint_as_float(cvt_tf32(p10));
                    smem[F_VT + (e+1)*STRIDE + lrow + 8] = __uint_as_float(cvt_tf32(p11));
                }
            }
        }
        __syncthreads();

        // ---- GEMM2: D2 += k^T x v'  (N=72, col 64 = norm sums) ----
        #pragma unroll
        for (int ks8 = 0; ks8 < 8; ++ks8) {
            uint32_t bf[9][2];
            #pragma unroll
            for (int nt = 0; nt < 9; ++nt) {
                const float* bp = smem + F_VT + (8*nt + (lane>>2))*STRIDE + 8*ks8 + (lane&3);
                bf[nt][0] = __float_as_uint(bp[0]);
                bf[nt][1] = __float_as_uint(bp[4]);
            }
            // A = k^T : read k_ transposed; m = 16w + lane/4 (+8), k = 8ks8 + lane%4 (+4)
            const float* ap = k_ + (8*ks8 + (lane&3))*STRIDE + 16*w + (lane>>2);
            uint32_t a0 = __float_as_uint(ap[0]);
            uint32_t a1 = __float_as_uint(ap[8]);
            uint32_t a2 = __float_as_uint(ap[4*STRIDE]);
            uint32_t a3 = __float_as_uint(ap[4*STRIDE + 8]);
            #pragma unroll
            for (int nt = 0; nt < 9; ++nt)
                mma8(d2[nt], a0, a1, a2, a3, bf[nt][0], bf[nt][1]);
        }
        __syncthreads();   // all reads of this tile's buffers done before next stage/epilogue
    }

    // ---- flush D2: new_kv (+past via memcpy seed) and new_norm ----
    {
        float* okv = dout + OUTG_ELEMS + (size_t)bh * (DD*EE);
        int dr = 16*w + (lane >> 2);
        #pragma unroll
        for (int nt = 0; nt < 8; ++nt) {
            int e = 8*nt + 2*(lane & 3);
            atomicAdd(okv + dr*EE + e,        d2[nt][0]);
            atomicAdd(okv + dr*EE + e + 1,    d2[nt][1]);
            atomicAdd(okv + (dr+8)*EE + e,    d2[nt][2]);
            atomicAdd(okv + (dr+8)*EE + e+1,  d2[nt][3]);
        }
        if ((lane & 3) == 0) {
            float* on = dout + OUTG_ELEMS + KV_ELEMS + bh*DD;
            atomicAdd(on + dr,     d2[8][0]);
            atomicAdd(on + dr + 8, d2[8][2]);
        }
    }
}

extern "C" void kernel_launch(void* const* d_in, const int* in_sizes, int n_in,
                              void* d_out, int out_size)
{
    const float* keys      = (const float*)d_in[0];
    const float* values    = (const float*)d_in[1];
    const float* queries   = (const float*)d_in[2];
    const float* outp      = (const float*)d_in[3];
    const float* past_kv   = (const float*)d_in[4];
    const float* past_norm = (const float*)d_in[5];
    const float* gates     = (const float*)d_in[6];
    float* dout = (float*)d_out;

    // Seed new_kv / new_norm output regions (atomics add partials on top)
    cudaMemcpyAsync(dout + OUTG_ELEMS, past_kv, KV_ELEMS * sizeof(float),
                    cudaMemcpyDeviceToDevice);
    cudaMemcpyAsync(dout + OUTG_ELEMS + KV_ELEMS, past_norm, NORM_ELEMS * sizeof(float),
                    cudaMemcpyDeviceToDevice);

    cudaFuncSetAttribute(fw_kernel, cudaFuncAttributeMaxDynamicSharedMemorySize, SMEM_BYTES);

    dim3 grid(CHUNKS, BH);
    fw_kernel<<<grid, THREADS, SMEM_BYTES>>>(keys, values, queries, outp,
                                             past_kv, past_norm, gates, dout);
}